// round 1
// baseline (speedup 1.0000x reference)
#include <cuda_runtime.h>
#include <math.h>

// Problem constants
#define Bb 4
#define Ss 2048
#define Ee 768
#define Hh 3
#define Dd 256
#define BHh 12   // Bb*Hh

// 1/sqrt(2048)
#define SCALE 0.022097086912079608f

// ---------------- scratch (device globals; no cudaMalloc allowed) ----------------
__device__ float g_Wr[3][Ee * Ee];                       // [E][H*D] permuted weights: 0=WK,1=WV,2=WQ
__device__ float g_P[3][Bb * Ss * Ee];                   // projections in [b,s,h,d]: 0=K,1=V,2=Q
__device__ float g_scores[(size_t)BHh * Ss * Ss];        // [z][S][S] scores -> probs (in place)
__device__ float g_concat[Bb * Ss * Ee];                 // [b,s,h*D+d]

// ---------------- weight permute: [H,E,D] -> [E, H*D] for all 3 matrices ----------------
__global__ void transpose_weights(const float* __restrict__ WK,
                                  const float* __restrict__ WV,
                                  const float* __restrict__ WQ) {
    int idx = blockIdx.x * blockDim.x + threadIdx.x;
    const int total = Hh * Ee * Dd;
    if (idx >= total) return;
    int h = idx / (Ee * Dd);
    int r = idx % (Ee * Dd);
    int e = r / Dd;
    int d = r % Dd;
    int dst = e * Ee + h * Dd + d;
    g_Wr[0][dst] = WK[idx];
    g_Wr[1][dst] = WV[idx];
    g_Wr[2][dst] = WQ[idx];
}

// ---------------- shared SGEMM cores (128x128 tile, BK=8, 256 thr, 8x8/thread) ----------------

// NN: A row-major [.., lda], B row-major [K x .., ldb]. kLen multiple of 8.
__device__ __forceinline__ void gemm_tiles_nn(
    const float* __restrict__ Aptr0, int lda,
    const float* __restrict__ Bptr0, int ldb,
    int kLen, float (*As)[128], float (*Bs)[128], float acc[8][8]) {
    int tid = threadIdx.x;
    int aRow = tid >> 1, aCol = (tid & 1) * 4;
    int bRow = tid >> 5, bCol = (tid & 31) * 4;
    int ty = tid >> 4, tx = tid & 15;
    const float* Aptr = Aptr0 + aRow * lda + aCol;
    const float* Bptr = Bptr0 + bRow * ldb + bCol;
    for (int k0 = 0; k0 < kLen; k0 += 8) {
        float4 av = *(const float4*)Aptr;
        As[aCol + 0][aRow] = av.x;
        As[aCol + 1][aRow] = av.y;
        As[aCol + 2][aRow] = av.z;
        As[aCol + 3][aRow] = av.w;
        *(float4*)&Bs[bRow][bCol] = *(const float4*)Bptr;
        __syncthreads();
#pragma unroll
        for (int kk = 0; kk < 8; kk++) {
            float ar[8], br[8];
#pragma unroll
            for (int i = 0; i < 8; i++) ar[i] = As[kk][ty * 8 + i];
#pragma unroll
            for (int j = 0; j < 8; j++) br[j] = Bs[kk][tx * 8 + j];
#pragma unroll
            for (int i = 0; i < 8; i++)
#pragma unroll
                for (int j = 0; j < 8; j++)
                    acc[i][j] = fmaf(ar[i], br[j], acc[i][j]);
        }
        __syncthreads();
        Aptr += 8;
        Bptr += 8 * ldb;
    }
}

// NT: B is row-major [N x K] (we need B^T). Both tiles loaded like A.
__device__ __forceinline__ void gemm_tiles_nt(
    const float* __restrict__ Aptr0, int lda,
    const float* __restrict__ Bptr0, int ldb,
    int kLen, float (*As)[128], float (*Bs)[128], float acc[8][8]) {
    int tid = threadIdx.x;
    int aRow = tid >> 1, aCol = (tid & 1) * 4;
    int ty = tid >> 4, tx = tid & 15;
    const float* Aptr = Aptr0 + aRow * lda + aCol;
    const float* Bptr = Bptr0 + aRow * ldb + aCol;  // same pattern: row=n index, col=k
    for (int k0 = 0; k0 < kLen; k0 += 8) {
        float4 av = *(const float4*)Aptr;
        As[aCol + 0][aRow] = av.x;
        As[aCol + 1][aRow] = av.y;
        As[aCol + 2][aRow] = av.z;
        As[aCol + 3][aRow] = av.w;
        float4 bv = *(const float4*)Bptr;
        Bs[aCol + 0][aRow] = bv.x;
        Bs[aCol + 1][aRow] = bv.y;
        Bs[aCol + 2][aRow] = bv.z;
        Bs[aCol + 3][aRow] = bv.w;
        __syncthreads();
#pragma unroll
        for (int kk = 0; kk < 8; kk++) {
            float ar[8], br[8];
#pragma unroll
            for (int i = 0; i < 8; i++) ar[i] = As[kk][ty * 8 + i];
#pragma unroll
            for (int j = 0; j < 8; j++) br[j] = Bs[kk][tx * 8 + j];
#pragma unroll
            for (int i = 0; i < 8; i++)
#pragma unroll
                for (int j = 0; j < 8; j++)
                    acc[i][j] = fmaf(ar[i], br[j], acc[i][j]);
        }
        __syncthreads();
        Aptr += 8;
        Bptr += 8;
    }
}

// ---------------- projections: X[8192x768] @ Wr[768x768] -> g_P[m] ([b,s,h,d]) ----------------
__global__ __launch_bounds__(256) void sgemm_proj(const float* __restrict__ X, int m) {
    __shared__ float As[8][128];
    __shared__ float Bs[8][128];
    int rowBase = blockIdx.y * 128;
    int colBase = blockIdx.x * 128;
    float acc[8][8] = {};
    gemm_tiles_nn(X + (size_t)rowBase * Ee, Ee, g_Wr[m] + colBase, Ee, Ee, As, Bs, acc);
    int ty = threadIdx.x >> 4, tx = threadIdx.x & 15;
    float* C = g_P[m];
#pragma unroll
    for (int i = 0; i < 8; i++) {
        int r = rowBase + ty * 8 + i;
#pragma unroll
        for (int j = 0; j < 8; j += 4) {
            int c = colBase + tx * 8 + j;
            float4 v = make_float4(acc[i][j], acc[i][j + 1], acc[i][j + 2], acc[i][j + 3]);
            *(float4*)&C[(size_t)r * Ee + c] = v;
        }
    }
}

// ---------------- scores: Q @ K^T * scale, causal tile skip ----------------
__global__ __launch_bounds__(256) void sgemm_scores() {
    int bx = blockIdx.x, by = blockIdx.y, z = blockIdx.z;
    if (bx > by) return;  // tile entirely above diagonal
    __shared__ float As[8][128];
    __shared__ float Bs[8][128];
    int b = z / Hh, h = z % Hh;
    int rowBase = by * 128;  // query rows
    int colBase = bx * 128;  // key cols
    size_t base = (size_t)b * Ss * Ee + (size_t)h * Dd;
    const float* Aptr0 = g_P[2] + base + (size_t)rowBase * Ee;  // Q
    const float* Bptr0 = g_P[0] + base + (size_t)colBase * Ee;  // K
    float acc[8][8] = {};
    gemm_tiles_nt(Aptr0, Ee, Bptr0, Ee, Dd, As, Bs, acc);
    int ty = threadIdx.x >> 4, tx = threadIdx.x & 15;
    float* C = g_scores + (size_t)z * Ss * Ss;
#pragma unroll
    for (int i = 0; i < 8; i++) {
        int r = rowBase + ty * 8 + i;
#pragma unroll
        for (int j = 0; j < 8; j += 4) {
            int c = colBase + tx * 8 + j;
            float4 v = make_float4(acc[i][j] * SCALE, acc[i][j + 1] * SCALE,
                                   acc[i][j + 2] * SCALE, acc[i][j + 3] * SCALE);
            *(float4*)&C[(size_t)r * Ss + c] = v;
        }
    }
}

// ---------------- causal row softmax (in place in g_scores; zeros above diag) ----------------
__device__ __forceinline__ float block_reduce_max(float v, float* red) {
#pragma unroll
    for (int o = 16; o; o >>= 1) v = fmaxf(v, __shfl_xor_sync(0xffffffffu, v, o));
    int tid = threadIdx.x;
    if ((tid & 31) == 0) red[tid >> 5] = v;
    __syncthreads();
    v = red[0];
#pragma unroll
    for (int w = 1; w < 8; w++) v = fmaxf(v, red[w]);
    __syncthreads();
    return v;
}

__device__ __forceinline__ float block_reduce_sum(float v, float* red) {
#pragma unroll
    for (int o = 16; o; o >>= 1) v += __shfl_xor_sync(0xffffffffu, v, o);
    int tid = threadIdx.x;
    if ((tid & 31) == 0) red[tid >> 5] = v;
    __syncthreads();
    v = red[0];
#pragma unroll
    for (int w = 1; w < 8; w++) v += red[w];
    __syncthreads();
    return v;
}

__global__ __launch_bounds__(256) void softmax_rows() {
    __shared__ float red[8];
    int gid = blockIdx.x;
    int z = gid >> 11;      // / 2048
    int i = gid & 2047;
    float* row = g_scores + (size_t)z * Ss * Ss + (size_t)i * Ss;
    int L = i + 1;
    int tid = threadIdx.x;
    float m = -3.4e38f;
    for (int j = tid; j < L; j += 256) m = fmaxf(m, row[j]);
    m = block_reduce_max(m, red);
    float s = 0.f;
    for (int j = tid; j < L; j += 256) s += __expf(row[j] - m);
    s = block_reduce_sum(s, red);
    float inv = 1.0f / s;
    for (int j = tid; j < Ss; j += 256)
        row[j] = (j < L) ? __expf(row[j] - m) * inv : 0.0f;
}

// ---------------- P @ V -> concat [b,s,h*D+d], causal K-limit ----------------
__global__ __launch_bounds__(256) void sgemm_pv() {
    __shared__ float As[8][128];
    __shared__ float Bs[8][128];
    int bx = blockIdx.x, by = blockIdx.y, z = blockIdx.z;
    int b = z / Hh, h = z % Hh;
    int rowBase = by * 128;   // query rows
    int colBase = bx * 128;   // d cols (0 or 128)
    const float* Aptr0 = g_scores + (size_t)z * Ss * Ss + (size_t)rowBase * Ss;
    size_t vbase = (size_t)b * Ss * Ee + (size_t)h * Dd;
    const float* Bptr0 = g_P[1] + vbase + colBase;  // V
    int kEnd = rowBase + 128;  // probs zero beyond causal bound
    float acc[8][8] = {};
    gemm_tiles_nn(Aptr0, Ss, Bptr0, Ee, kEnd, As, Bs, acc);
    int ty = threadIdx.x >> 4, tx = threadIdx.x & 15;
    float* C = g_concat + vbase;
#pragma unroll
    for (int i = 0; i < 8; i++) {
        int r = rowBase + ty * 8 + i;
#pragma unroll
        for (int j = 0; j < 8; j += 4) {
            int c = colBase + tx * 8 + j;
            float4 v = make_float4(acc[i][j], acc[i][j + 1], acc[i][j + 2], acc[i][j + 3]);
            *(float4*)&C[(size_t)r * Ee + c] = v;
        }
    }
}

// ---------------- output GEMM: concat @ Wo + bo ----------------
__global__ __launch_bounds__(256) void sgemm_out(const float* __restrict__ Wo,
                                                 const float* __restrict__ bo,
                                                 float* __restrict__ out) {
    __shared__ float As[8][128];
    __shared__ float Bs[8][128];
    int rowBase = blockIdx.y * 128;
    int colBase = blockIdx.x * 128;
    float acc[8][8] = {};
    gemm_tiles_nn(g_concat + (size_t)rowBase * Ee, Ee, Wo + colBase, Ee, Ee, As, Bs, acc);
    int ty = threadIdx.x >> 4, tx = threadIdx.x & 15;
#pragma unroll
    for (int i = 0; i < 8; i++) {
        int r = rowBase + ty * 8 + i;
#pragma unroll
        for (int j = 0; j < 8; j += 4) {
            int c = colBase + tx * 8 + j;
            float4 v = make_float4(acc[i][j] + bo[c], acc[i][j + 1] + bo[c + 1],
                                   acc[i][j + 2] + bo[c + 2], acc[i][j + 3] + bo[c + 3]);
            *(float4*)&out[(size_t)r * Ee + c] = v;
        }
    }
}

// ---------------- launch ----------------
extern "C" void kernel_launch(void* const* d_in, const int* in_sizes, int n_in,
                              void* d_out, int out_size) {
    const float* Xk = (const float*)d_in[0];
    const float* Xv = (const float*)d_in[1];
    const float* Xq = (const float*)d_in[2];
    const float* WK = (const float*)d_in[3];
    const float* WV = (const float*)d_in[4];
    const float* WQ = (const float*)d_in[5];
    const float* Wo = (const float*)d_in[6];
    const float* bo = (const float*)d_in[7];
    float* out = (float*)d_out;

    // 1) permute weights [H,E,D] -> [E, H*D]
    transpose_weights<<<(Hh * Ee * Dd + 255) / 256, 256>>>(WK, WV, WQ);

    // 2) projections: M=8192, N=768, K=768
    dim3 gProj(Ee / 128, (Bb * Ss) / 128);
    sgemm_proj<<<gProj, 256>>>(Xk, 0);
    sgemm_proj<<<gProj, 256>>>(Xv, 1);
    sgemm_proj<<<gProj, 256>>>(Xq, 2);

    // 3) scores = Q K^T * scale (causal tile skip), batched over 12 (b,h)
    dim3 gSc(Ss / 128, Ss / 128, BHh);
    sgemm_scores<<<gSc, 256>>>();

    // 4) causal softmax per row
    softmax_rows<<<BHh * Ss, 256>>>();

    // 5) Z = probs @ V -> concat, causal K-limit
    dim3 gPv(Dd / 128, Ss / 128, BHh);
    sgemm_pv<<<gPv, 256>>>();

    // 6) out = concat @ Wo + bo
    dim3 gOut(Ee / 128, (Bb * Ss) / 128);
    sgemm_out<<<gOut, 256>>>(Wo, bo, out);
}

// round 3
// speedup vs baseline: 3.2905x; 3.2905x over previous
#include <cuda_runtime.h>
#include <cuda_bf16.h>
#include <cstdint>

// ---------------- problem constants ----------------
#define Bb 4
#define Ss 2048
#define Ee 768
#define Hh 3
#define Dd 256
#define BHh 12
#define SCALE 0.022097086912079608f   // 1/sqrt(2048)

#define NE (8192 * 768)
#define EE (768 * 768)

// ---------------- scratch (device globals; no cudaMalloc allowed) ----------------
__device__ __align__(16) __nv_bfloat16 g_Xhi[3][NE];
__device__ __align__(16) __nv_bfloat16 g_Xlo[3][NE];
__device__ __align__(16) __nv_bfloat16 g_Wthi[3][EE];   // W^T: [n=h*256+d][k=e]
__device__ __align__(16) __nv_bfloat16 g_Wtlo[3][EE];
__device__ __align__(16) __nv_bfloat16 g_Wohi[EE];      // Wo^T: [n=eout][k=ein]
__device__ __align__(16) __nv_bfloat16 g_Wolo[EE];
__device__ __align__(16) __nv_bfloat16 g_Qhi[BHh * Ss * Dd];  // [z][s][d]
__device__ __align__(16) __nv_bfloat16 g_Qlo[BHh * Ss * Dd];
__device__ __align__(16) __nv_bfloat16 g_Khi[BHh * Ss * Dd];
__device__ __align__(16) __nv_bfloat16 g_Klo[BHh * Ss * Dd];
__device__ __align__(16) __nv_bfloat16 g_Vthi[BHh * Dd * Ss]; // [z][d][s]
__device__ __align__(16) __nv_bfloat16 g_Vtlo[BHh * Dd * Ss];
__device__ float g_scores[(size_t)BHh * Ss * Ss];
__device__ __align__(16) __nv_bfloat16 g_Phi[(size_t)BHh * Ss * Ss];
__device__ __align__(16) __nv_bfloat16 g_Plo[(size_t)BHh * Ss * Ss];
__device__ __align__(16) __nv_bfloat16 g_Chi[NE];
__device__ __align__(16) __nv_bfloat16 g_Clo[NE];

// ---------------- helpers ----------------
__device__ __forceinline__ uint32_t smem_u32(const void* p) {
    uint32_t a;
    asm("{ .reg .u64 t; cvta.to.shared.u64 t, %1; cvt.u32.u64 %0, t; }" : "=r"(a) : "l"(p));
    return a;
}
__device__ __forceinline__ void ldsm4(uint32_t r[4], uint32_t addr) {
    asm volatile("ldmatrix.sync.aligned.m8n8.x4.shared.b16 {%0,%1,%2,%3}, [%4];"
                 : "=r"(r[0]), "=r"(r[1]), "=r"(r[2]), "=r"(r[3]) : "r"(addr));
}
__device__ __forceinline__ void mma16816(float c[4], const uint32_t a[4], uint32_t b0, uint32_t b1) {
    asm volatile("mma.sync.aligned.m16n8k16.row.col.f32.bf16.bf16.f32 "
                 "{%0,%1,%2,%3}, {%4,%5,%6,%7}, {%8,%9}, {%0,%1,%2,%3};"
                 : "+f"(c[0]), "+f"(c[1]), "+f"(c[2]), "+f"(c[3])
                 : "r"(a[0]), "r"(a[1]), "r"(a[2]), "r"(a[3]), "r"(b0), "r"(b1));
}
__device__ __forceinline__ void split2(float x, __nv_bfloat16& hi, __nv_bfloat16& lo) {
    hi = __float2bfloat16(x);
    lo = __float2bfloat16(x - __bfloat162float(hi));
}

// ---------------- conversion kernels ----------------
__global__ __launch_bounds__(256) void conv_inputs(const float* __restrict__ Xk,
                                                   const float* __restrict__ Xv,
                                                   const float* __restrict__ Xq) {
    int i = blockIdx.x * blockDim.x + threadIdx.x;
    if (i >= NE) return;
    __nv_bfloat16 hi, lo;
    split2(Xk[i], hi, lo); g_Xhi[0][i] = hi; g_Xlo[0][i] = lo;
    split2(Xv[i], hi, lo); g_Xhi[1][i] = hi; g_Xlo[1][i] = lo;
    split2(Xq[i], hi, lo); g_Xhi[2][i] = hi; g_Xlo[2][i] = lo;
}

__global__ __launch_bounds__(256) void conv_weights(const float* __restrict__ WK,
                                                    const float* __restrict__ WV,
                                                    const float* __restrict__ WQ,
                                                    const float* __restrict__ Wo) {
    int i = blockIdx.x * blockDim.x + threadIdx.x;
    if (i >= EE) return;
    int h = i / (Ee * Dd);
    int r = i % (Ee * Dd);
    int e = r / Dd;
    int d = r % Dd;
    int dst = (h * Dd + d) * Ee + e;
    __nv_bfloat16 hi, lo;
    split2(WK[i], hi, lo); g_Wthi[0][dst] = hi; g_Wtlo[0][dst] = lo;
    split2(WV[i], hi, lo); g_Wthi[1][dst] = hi; g_Wtlo[1][dst] = lo;
    split2(WQ[i], hi, lo); g_Wthi[2][dst] = hi; g_Wtlo[2][dst] = lo;
    int k = i / Ee, n = i % Ee;
    split2(Wo[i], hi, lo); g_Wohi[n * Ee + k] = hi; g_Wolo[n * Ee + k] = lo;
}

// ---------------- mma.sync GEMM core ----------------
// 128x128 block tile, BK=32, 256 threads, 8 warps (2M x 4N), warp tile 64x32.
// A row-major [m][k] (lda), B NT row-major [n][k] (ldb). smem rows padded to 40 bf16.
struct Seg { const __nv_bfloat16* A; const __nv_bfloat16* B; int klen; };

#define STAGE_BYTES 20480   // A(128*40*2=10240) + B(10240)

__device__ __forceinline__ void load_tiles(uint32_t sA, uint32_t sB,
                                           const __nv_bfloat16* __restrict__ A, int lda,
                                           const __nv_bfloat16* __restrict__ B, int ldb,
                                           int k0) {
    int tid = threadIdx.x;
#pragma unroll
    for (int c = 0; c < 2; c++) {
        int idx = tid + c * 256;        // [0,512): A chunks
        int row = idx >> 2, ch = idx & 3;
        const void* src = A + (size_t)row * lda + k0 + ch * 8;
        asm volatile("cp.async.cg.shared.global [%0], [%1], 16;"
                     :: "r"(sA + row * 80 + ch * 16), "l"(src));
    }
#pragma unroll
    for (int c = 0; c < 2; c++) {
        int idx = tid + c * 256;
        int row = idx >> 2, ch = idx & 3;
        const void* src = B + (size_t)row * ldb + k0 + ch * 8;
        asm volatile("cp.async.cg.shared.global [%0], [%1], 16;"
                     :: "r"(sB + row * 80 + ch * 16), "l"(src));
    }
    asm volatile("cp.async.commit_group;");
}

__device__ __forceinline__ void compute_stage(uint32_t sA, uint32_t sB,
                                              float acc[4][4][4], int wm, int wn, int lane) {
#pragma unroll
    for (int ks = 0; ks < 2; ks++) {
        uint32_t a[4][4];
#pragma unroll
        for (int mi = 0; mi < 4; mi++) {
            uint32_t addr = sA + (wm + mi * 16 + (lane & 15)) * 80 + ((lane >> 4) << 4) + ks * 32;
            ldsm4(a[mi], addr);
        }
        uint32_t b[2][4];
#pragma unroll
        for (int nj = 0; nj < 2; nj++) {
            uint32_t addr = sB + (wn + nj * 16 + (lane & 7) + ((lane >> 4) & 1) * 8) * 80 +
                            ((lane >> 3) & 1) * 16 + ks * 32;
            ldsm4(b[nj], addr);
        }
#pragma unroll
        for (int mi = 0; mi < 4; mi++)
#pragma unroll
            for (int ni = 0; ni < 4; ni++)
                mma16816(acc[mi][ni], a[mi], b[ni >> 1][(ni & 1) * 2], b[ni >> 1][(ni & 1) * 2 + 1]);
    }
}

__device__ __forceinline__ void gemm_run(const Seg seg[3], int lda, int ldb,
                                         uint32_t sbase, float acc[4][4][4],
                                         int wm, int wn, int lane) {
    int total = (seg[0].klen + seg[1].klen + seg[2].klen) >> 5;
    int si = 0, k = 0;
    load_tiles(sbase, sbase + 10240, seg[0].A, lda, seg[0].B, ldb, 0);
    k = 32;
    if (k >= seg[0].klen) { k = 0; si = 1; }
    for (int t = 0; t < total; t++) {
        uint32_t cur = sbase + (t & 1) * STAGE_BYTES;
        if (t + 1 < total) {
            uint32_t nxt = sbase + ((t + 1) & 1) * STAGE_BYTES;
            load_tiles(nxt, nxt + 10240, seg[si].A, lda, seg[si].B, ldb, k);
            k += 32;
            if (k >= seg[si].klen) { k = 0; si++; }
            asm volatile("cp.async.wait_group 1;");
        } else {
            asm volatile("cp.async.wait_group 0;");
        }
        __syncthreads();
        compute_stage(cur, cur + 10240, acc, wm, wn, lane);
        __syncthreads();
    }
}

// ---------------- projections ----------------
__global__ __launch_bounds__(256, 2) void mma_proj(int m) {
    __shared__ __align__(16) __nv_bfloat16 sm[2][2][5120];
    int tid = threadIdx.x, lane = tid & 31, w = tid >> 5;
    int wm = (w & 1) * 64, wn = (w >> 1) * 32;
    uint32_t sbase = smem_u32(sm);
    int rowBase = blockIdx.y * 128, colBase = blockIdx.x * 128;
    float acc[4][4][4] = {};
    Seg seg[3] = {
        { g_Xhi[m] + (size_t)rowBase * Ee, g_Wthi[m] + (size_t)colBase * Ee, Ee },
        { g_Xlo[m] + (size_t)rowBase * Ee, g_Wthi[m] + (size_t)colBase * Ee, Ee },
        { g_Xhi[m] + (size_t)rowBase * Ee, g_Wtlo[m] + (size_t)colBase * Ee, Ee } };
    gemm_run(seg, Ee, Ee, sbase, acc, wm, wn, lane);

    int lr = lane >> 2, lc = (lane & 3) * 2;
#pragma unroll
    for (int mi = 0; mi < 4; mi++)
#pragma unroll
        for (int ni = 0; ni < 4; ni++)
#pragma unroll
            for (int half = 0; half < 2; half++) {
                int gr = rowBase + wm + mi * 16 + lr + half * 8;
                int b = gr >> 11, sI = gr & 2047;
                int col = colBase + wn + ni * 8 + lc;
                int h = col >> 8, d = col & 255;
                int z = b * Hh + h;
                float v0 = acc[mi][ni][half * 2], v1 = acc[mi][ni][half * 2 + 1];
                __nv_bfloat16 h0, l0, h1, l1;
                split2(v0, h0, l0);
                split2(v1, h1, l1);
                if (m == 1) {
                    size_t d0 = ((size_t)z * Dd + d) * Ss + sI;
                    size_t d1 = ((size_t)z * Dd + d + 1) * Ss + sI;
                    g_Vthi[d0] = h0; g_Vtlo[d0] = l0;
                    g_Vthi[d1] = h1; g_Vtlo[d1] = l1;
                } else {
                    size_t dst = ((size_t)z * Ss + sI) * Dd + d;
                    if (m == 0) { g_Khi[dst] = h0; g_Klo[dst] = l0;
                                  g_Khi[dst + 1] = h1; g_Klo[dst + 1] = l1; }
                    else        { g_Qhi[dst] = h0; g_Qlo[dst] = l0;
                                  g_Qhi[dst + 1] = h1; g_Qlo[dst + 1] = l1; }
                }
            }
}

// ---------------- scores = Q K^T * SCALE (causal tile skip) ----------------
__global__ __launch_bounds__(256, 2) void mma_scores() {
    if (blockIdx.x > blockIdx.y) return;
    __shared__ __align__(16) __nv_bfloat16 sm[2][2][5120];
    int tid = threadIdx.x, lane = tid & 31, w = tid >> 5;
    int wm = (w & 1) * 64, wn = (w >> 1) * 32;
    uint32_t sbase = smem_u32(sm);
    int z = blockIdx.z;
    int rowBase = blockIdx.y * 128, colBase = blockIdx.x * 128;
    size_t qo = (size_t)z * Ss * Dd;
    const __nv_bfloat16* Qh = g_Qhi + qo + (size_t)rowBase * Dd;
    const __nv_bfloat16* Ql = g_Qlo + qo + (size_t)rowBase * Dd;
    const __nv_bfloat16* Kh = g_Khi + qo + (size_t)colBase * Dd;
    const __nv_bfloat16* Kl = g_Klo + qo + (size_t)colBase * Dd;
    float acc[4][4][4] = {};
    Seg seg[3] = { { Qh, Kh, Dd }, { Ql, Kh, Dd }, { Qh, Kl, Dd } };
    gemm_run(seg, Dd, Dd, sbase, acc, wm, wn, lane);

    float* C = g_scores + (size_t)z * Ss * Ss;
    int lr = lane >> 2, lc = (lane & 3) * 2;
#pragma unroll
    for (int mi = 0; mi < 4; mi++)
#pragma unroll
        for (int ni = 0; ni < 4; ni++)
#pragma unroll
            for (int half = 0; half < 2; half++) {
                int gr = rowBase + wm + mi * 16 + lr + half * 8;
                int col = colBase + wn + ni * 8 + lc;
                float2 v = make_float2(acc[mi][ni][half * 2] * SCALE,
                                       acc[mi][ni][half * 2 + 1] * SCALE);
                *(float2*)&C[(size_t)gr * Ss + col] = v;
            }
}

// ---------------- causal softmax; writes P as hi/lo bf16 ----------------
__global__ __launch_bounds__(256) void softmax_rows() {
    __shared__ float red[8];
    int gid = blockIdx.x;
    int z = gid >> 11;
    int i = gid & 2047;
    size_t ro = (size_t)z * Ss * Ss + (size_t)i * Ss;
    const float* row = g_scores + ro;
    int L = i + 1;
    int tid = threadIdx.x;
    float mx = -3.4e38f;
    for (int j = tid; j < L; j += 256) mx = fmaxf(mx, row[j]);
#pragma unroll
    for (int o = 16; o; o >>= 1) mx = fmaxf(mx, __shfl_xor_sync(0xffffffffu, mx, o));
    if ((tid & 31) == 0) red[tid >> 5] = mx;
    __syncthreads();
    mx = red[0];
#pragma unroll
    for (int ww = 1; ww < 8; ww++) mx = fmaxf(mx, red[ww]);
    __syncthreads();
    float sum = 0.f;
    for (int j = tid; j < L; j += 256) sum += __expf(row[j] - mx);
#pragma unroll
    for (int o = 16; o; o >>= 1) sum += __shfl_xor_sync(0xffffffffu, sum, o);
    if ((tid & 31) == 0) red[tid >> 5] = sum;
    __syncthreads();
    sum = red[0];
#pragma unroll
    for (int ww = 1; ww < 8; ww++) sum += red[ww];
    float inv = 1.0f / sum;
    for (int j = tid; j < Ss; j += 256) {
        float p = (j < L) ? __expf(row[j] - mx) * inv : 0.0f;
        __nv_bfloat16 hi, lo;
        split2(p, hi, lo);
        g_Phi[ro + j] = hi;
        g_Plo[ro + j] = lo;
    }
}

// ---------------- Z = P V (causal K-limit) -> concat hi/lo ----------------
__global__ __launch_bounds__(256, 2) void mma_pv() {
    __shared__ __align__(16) __nv_bfloat16 sm[2][2][5120];
    int tid = threadIdx.x, lane = tid & 31, w = tid >> 5;
    int wm = (w & 1) * 64, wn = (w >> 1) * 32;
    uint32_t sbase = smem_u32(sm);
    int z = blockIdx.z;
    int rowBase = blockIdx.y * 128, colBase = blockIdx.x * 128;
    int kEnd = rowBase + 128;
    const __nv_bfloat16* Ph = g_Phi + (size_t)z * Ss * Ss + (size_t)rowBase * Ss;
    const __nv_bfloat16* Pl = g_Plo + (size_t)z * Ss * Ss + (size_t)rowBase * Ss;
    const __nv_bfloat16* Vh = g_Vthi + (size_t)z * Dd * Ss + (size_t)colBase * Ss;
    const __nv_bfloat16* Vl = g_Vtlo + (size_t)z * Dd * Ss + (size_t)colBase * Ss;
    float acc[4][4][4] = {};
    Seg seg[3] = { { Ph, Vh, kEnd }, { Pl, Vh, kEnd }, { Ph, Vl, kEnd } };
    gemm_run(seg, Ss, Ss, sbase, acc, wm, wn, lane);

    int b = z / Hh, h = z % Hh;
    int lr = lane >> 2, lc = (lane & 3) * 2;
#pragma unroll
    for (int mi = 0; mi < 4; mi++)
#pragma unroll
        for (int ni = 0; ni < 4; ni++)
#pragma unroll
            for (int half = 0; half < 2; half++) {
                int sI = rowBase + wm + mi * 16 + lr + half * 8;
                int d = colBase + wn + ni * 8 + lc;
                __nv_bfloat16 h0, l0, h1, l1;
                split2(acc[mi][ni][half * 2], h0, l0);
                split2(acc[mi][ni][half * 2 + 1], h1, l1);
                size_t dst = ((size_t)(b * Ss + sI)) * Ee + h * Dd + d;
                g_Chi[dst] = h0; g_Clo[dst] = l0;
                g_Chi[dst + 1] = h1; g_Clo[dst + 1] = l1;
            }
}

// ---------------- out = concat @ Wo + bo ----------------
__global__ __launch_bounds__(256, 2) void mma_out(const float* __restrict__ bo,
                                                  float* __restrict__ out) {
    __shared__ __align__(16) __nv_bfloat16 sm[2][2][5120];
    int tid = threadIdx.x, lane = tid & 31, w = tid >> 5;
    int wm = (w & 1) * 64, wn = (w >> 1) * 32;
    uint32_t sbase = smem_u32(sm);
    int rowBase = blockIdx.y * 128, colBase = blockIdx.x * 128;
    float acc[4][4][4] = {};
    Seg seg[3] = {
        { g_Chi + (size_t)rowBase * Ee, g_Wohi + (size_t)colBase * Ee, Ee },
        { g_Clo + (size_t)rowBase * Ee, g_Wohi + (size_t)colBase * Ee, Ee },
        { g_Chi + (size_t)rowBase * Ee, g_Wolo + (size_t)colBase * Ee, Ee } };
    gemm_run(seg, Ee, Ee, sbase, acc, wm, wn, lane);

    int lr = lane >> 2, lc = (lane & 3) * 2;
#pragma unroll
    for (int mi = 0; mi < 4; mi++)
#pragma unroll
        for (int ni = 0; ni < 4; ni++)
#pragma unroll
            for (int half = 0; half < 2; half++) {
                int gr = rowBase + wm + mi * 16 + lr + half * 8;
                int col = colBase + wn + ni * 8 + lc;
                float2 v = make_float2(acc[mi][ni][half * 2] + bo[col],
                                       acc[mi][ni][half * 2 + 1] + bo[col + 1]);
                *(float2*)&out[(size_t)gr * Ee + col] = v;
            }
}

// ---------------- launch ----------------
extern "C" void kernel_launch(void* const* d_in, const int* in_sizes, int n_in,
                              void* d_out, int out_size) {
    const float* Xk = (const float*)d_in[0];
    const float* Xv = (const float*)d_in[1];
    const float* Xq = (const float*)d_in[2];
    const float* WK = (const float*)d_in[3];
    const float* WV = (const float*)d_in[4];
    const float* WQ = (const float*)d_in[5];
    const float* Wo = (const float*)d_in[6];
    const float* bo = (const float*)d_in[7];
    float* out = (float*)d_out;

    conv_inputs<<<(NE + 255) / 256, 256>>>(Xk, Xv, Xq);
    conv_weights<<<(EE + 255) / 256, 256>>>(WK, WV, WQ, Wo);

    dim3 gProj(Ee / 128, (Bb * Ss) / 128);     // (6, 64)
    mma_proj<<<gProj, 256>>>(0);
    mma_proj<<<gProj, 256>>>(1);
    mma_proj<<<gProj, 256>>>(2);

    dim3 gSc(Ss / 128, Ss / 128, BHh);         // (16, 16, 12)
    mma_scores<<<gSc, 256>>>();

    softmax_rows<<<BHh * Ss, 256>>>();

    dim3 gPv(Dd / 128, Ss / 128, BHh);         // (2, 16, 12)
    mma_pv<<<gPv, 256>>>();

    dim3 gOut(Ee / 128, (Bb * Ss) / 128);      // (6, 64)
    mma_out<<<gOut, 256>>>(bo, out);
}